// round 1
// baseline (speedup 1.0000x reference)
#include <cuda_runtime.h>
#include <math.h>

// Problem constants
#define D_MODEL 512
#define HDIM    2048
#define TSEQ    4096
#define NB      2
#define NTOK    (NB * TSEQ)  // 8192

// -------- static scratch (allocation-free per harness rules) --------
__device__ float g_q[(size_t)NTOK * D_MODEL];
__device__ float g_k[(size_t)NTOK * D_MODEL];
__device__ float g_v[(size_t)NTOK * D_MODEL];
__device__ float g_attn[(size_t)NTOK * D_MODEL];
__device__ float g_x[(size_t)NTOK * D_MODEL];
__device__ float g_y[(size_t)NTOK * D_MODEL];
__device__ float g_h[(size_t)NTOK * HDIM];
__device__ float g_s[(size_t)NB * TSEQ * TSEQ];  // scores / probs (in-place softmax)

// ============================================================================
// Tiled SGEMM: C = A(MxK) @ B(KxN) [+bias] [relu], row-major, batched via z.
// BM=BN=128, BK=16, 256 threads, 8x8 per-thread tile.
// KLIMIT=1: K clamped to (blockIdx.y+1)*128 (causal P@V).
// ============================================================================
template <int RELU, int KLIMIT>
__global__ __launch_bounds__(256) void gemm_nn(
    const float* __restrict__ Aall, const float* __restrict__ Ball,
    const float* __restrict__ bias, float* __restrict__ Call,
    int M, int N, int K, long sA, long sB, long sC)
{
    __shared__ float As[16][128];
    __shared__ float Bs[16][128];

    const float* A = Aall + (size_t)blockIdx.z * sA;
    const float* B = Ball + (size_t)blockIdx.z * sB;
    float*       C = Call + (size_t)blockIdx.z * sC;

    const int tid = threadIdx.x;
    const int m0 = blockIdx.y * 128;
    const int n0 = blockIdx.x * 128;
    const int Keff = KLIMIT ? min(K, ((int)blockIdx.y + 1) * 128) : K;

    const int ty = tid >> 4;   // 0..15
    const int tx = tid & 15;   // 0..15

    float acc[8][8];
#pragma unroll
    for (int i = 0; i < 8; i++)
#pragma unroll
        for (int j = 0; j < 8; j++) acc[i][j] = 0.f;

    for (int kt = 0; kt < Keff; kt += 16) {
#pragma unroll
        for (int i = 0; i < 2; i++) {
            int idx = tid + i * 256;
            // A tile 128x16 -> As[k][m]
            int row = idx >> 2;
            int c4  = (idx & 3) << 2;
            float4 va = *(const float4*)(A + (size_t)(m0 + row) * K + kt + c4);
            As[c4 + 0][row] = va.x;
            As[c4 + 1][row] = va.y;
            As[c4 + 2][row] = va.z;
            As[c4 + 3][row] = va.w;
            // B tile 16x128 -> Bs[k][n]
            int brow = idx >> 5;
            int bc   = (idx & 31) << 2;
            *(float4*)&Bs[brow][bc] =
                *(const float4*)(B + (size_t)(kt + brow) * N + n0 + bc);
        }
        __syncthreads();

#pragma unroll
        for (int k = 0; k < 16; k++) {
            float a[8], b[8];
            *(float4*)&a[0] = *(const float4*)&As[k][ty * 8];
            *(float4*)&a[4] = *(const float4*)&As[k][ty * 8 + 4];
            *(float4*)&b[0] = *(const float4*)&Bs[k][tx * 8];
            *(float4*)&b[4] = *(const float4*)&Bs[k][tx * 8 + 4];
#pragma unroll
            for (int i = 0; i < 8; i++)
#pragma unroll
                for (int j = 0; j < 8; j++)
                    acc[i][j] = fmaf(a[i], b[j], acc[i][j]);
        }
        __syncthreads();
    }

#pragma unroll
    for (int i = 0; i < 8; i++) {
        int m = m0 + ty * 8 + i;
#pragma unroll
        for (int jv = 0; jv < 2; jv++) {
            int n = n0 + tx * 8 + jv * 4;
            float4 r;
            r.x = acc[i][jv * 4 + 0];
            r.y = acc[i][jv * 4 + 1];
            r.z = acc[i][jv * 4 + 2];
            r.w = acc[i][jv * 4 + 3];
            if (bias) {
                r.x += bias[n + 0];
                r.y += bias[n + 1];
                r.z += bias[n + 2];
                r.w += bias[n + 3];
            }
            if (RELU) {
                r.x = fmaxf(r.x, 0.f);
                r.y = fmaxf(r.y, 0.f);
                r.z = fmaxf(r.z, 0.f);
                r.w = fmaxf(r.w, 0.f);
            }
            *(float4*)(C + (size_t)m * N + n) = r;
        }
    }
}

// ============================================================================
// NT GEMM for scores: S = Q (TxD) @ K^T (DxT); batched; skips fully-masked
// (strictly above-diagonal) tiles. Raw scores only; softmax applies bias/scale.
// ============================================================================
__global__ __launch_bounds__(256) void gemm_nt_causal(
    const float* __restrict__ Qall, const float* __restrict__ Kall,
    float* __restrict__ Sall, int M, int N, int K)
{
    if (blockIdx.x > blockIdx.y) return;  // s-tile entirely above diagonal

    __shared__ float As[16][128];
    __shared__ float Bs[16][128];

    const int bz = blockIdx.z;
    const float* A  = Qall + (size_t)bz * M * K;
    const float* Bt = Kall + (size_t)bz * N * K;
    float*       C  = Sall + (size_t)bz * M * N;

    const int tid = threadIdx.x;
    const int m0 = blockIdx.y * 128;
    const int n0 = blockIdx.x * 128;
    const int ty = tid >> 4;
    const int tx = tid & 15;

    float acc[8][8];
#pragma unroll
    for (int i = 0; i < 8; i++)
#pragma unroll
        for (int j = 0; j < 8; j++) acc[i][j] = 0.f;

    for (int kt = 0; kt < K; kt += 16) {
#pragma unroll
        for (int i = 0; i < 2; i++) {
            int idx = tid + i * 256;
            int row = idx >> 2;
            int c4  = (idx & 3) << 2;
            float4 va = *(const float4*)(A + (size_t)(m0 + row) * K + kt + c4);
            As[c4 + 0][row] = va.x;
            As[c4 + 1][row] = va.y;
            As[c4 + 2][row] = va.z;
            As[c4 + 3][row] = va.w;
            float4 vb = *(const float4*)(Bt + (size_t)(n0 + row) * K + kt + c4);
            Bs[c4 + 0][row] = vb.x;
            Bs[c4 + 1][row] = vb.y;
            Bs[c4 + 2][row] = vb.z;
            Bs[c4 + 3][row] = vb.w;
        }
        __syncthreads();

#pragma unroll
        for (int k = 0; k < 16; k++) {
            float a[8], b[8];
            *(float4*)&a[0] = *(const float4*)&As[k][ty * 8];
            *(float4*)&a[4] = *(const float4*)&As[k][ty * 8 + 4];
            *(float4*)&b[0] = *(const float4*)&Bs[k][tx * 8];
            *(float4*)&b[4] = *(const float4*)&Bs[k][tx * 8 + 4];
#pragma unroll
            for (int i = 0; i < 8; i++)
#pragma unroll
                for (int j = 0; j < 8; j++)
                    acc[i][j] = fmaf(a[i], b[j], acc[i][j]);
        }
        __syncthreads();
    }

#pragma unroll
    for (int i = 0; i < 8; i++) {
        int m = m0 + ty * 8 + i;
#pragma unroll
        for (int jv = 0; jv < 2; jv++) {
            int n = n0 + tx * 8 + jv * 4;
            float4 r;
            r.x = acc[i][jv * 4 + 0];
            r.y = acc[i][jv * 4 + 1];
            r.z = acc[i][jv * 4 + 2];
            r.w = acc[i][jv * 4 + 3];
            *(float4*)(C + (size_t)m * N + n) = r;
        }
    }
}

// ============================================================================
// Row softmax (in-place): P[t,s] = softmax_s<=t((S - ds*(t-s)) / sqrt(d)),
// zeros for s > t. One block per (t, b) row.
// ============================================================================
__global__ __launch_bounds__(256) void softmax_kernel(
    float* __restrict__ S, const float* __restrict__ ds_ptr)
{
    __shared__ float sbuf[TSEQ];
    __shared__ float red[256];

    const int t = blockIdx.x;
    const int b = blockIdx.y;
    const int tid = threadIdx.x;
    float* row = S + ((size_t)b * TSEQ + t) * TSEQ;

    const float ds = *ds_ptr;
    const float scale = rsqrtf((float)D_MODEL);
    const int len = t + 1;

    float mx = -1e30f;
    for (int s = tid; s < len; s += 256) {
        float v = (row[s] - ds * (float)(t - s)) * scale;
        sbuf[s] = v;
        mx = fmaxf(mx, v);
    }
    red[tid] = mx;
    __syncthreads();
    for (int o = 128; o; o >>= 1) {
        if (tid < o) red[tid] = fmaxf(red[tid], red[tid + o]);
        __syncthreads();
    }
    mx = red[0];
    __syncthreads();

    float sum = 0.f;
    for (int s = tid; s < len; s += 256) sum += __expf(sbuf[s] - mx);
    red[tid] = sum;
    __syncthreads();
    for (int o = 128; o; o >>= 1) {
        if (tid < o) red[tid] += red[tid + o];
        __syncthreads();
    }
    const float inv = 1.0f / red[0];

    for (int s = tid; s < TSEQ; s += 256)
        row[s] = (s < len) ? __expf(sbuf[s] - mx) * inv : 0.f;
}

// ============================================================================
// LayerNorm over last dim (512): out = LN(A + R) * gamma + beta.
// One 128-thread block per row, 4 elems/thread.
// ============================================================================
__global__ __launch_bounds__(128) void ln_kernel(
    const float* __restrict__ A, const float* __restrict__ R,
    const float* __restrict__ gamma, const float* __restrict__ beta,
    float* __restrict__ out)
{
    __shared__ float sh[4];
    const int row = blockIdx.x;
    const int tid = threadIdx.x;
    const size_t base = (size_t)row * D_MODEL + tid * 4;

    float4 a = *(const float4*)(A + base);
    float4 r = *(const float4*)(R + base);
    float x0 = a.x + r.x, x1 = a.y + r.y, x2 = a.z + r.z, x3 = a.w + r.w;

    float s = x0 + x1 + x2 + x3;
    for (int o = 16; o; o >>= 1) s += __shfl_xor_sync(0xffffffffu, s, o);
    if ((tid & 31) == 0) sh[tid >> 5] = s;
    __syncthreads();
    const float mean = (sh[0] + sh[1] + sh[2] + sh[3]) * (1.0f / D_MODEL);
    __syncthreads();

    float d0 = x0 - mean, d1 = x1 - mean, d2 = x2 - mean, d3 = x3 - mean;
    float sq = d0 * d0 + d1 * d1 + d2 * d2 + d3 * d3;
    for (int o = 16; o; o >>= 1) sq += __shfl_xor_sync(0xffffffffu, sq, o);
    if ((tid & 31) == 0) sh[tid >> 5] = sq;
    __syncthreads();
    const float var = (sh[0] + sh[1] + sh[2] + sh[3]) * (1.0f / D_MODEL);
    const float rstd = rsqrtf(var + 1e-5f);

    float4 g  = *(const float4*)(gamma + tid * 4);
    float4 be = *(const float4*)(beta + tid * 4);
    float4 o4;
    o4.x = d0 * rstd * g.x + be.x;
    o4.y = d1 * rstd * g.y + be.y;
    o4.z = d2 * rstd * g.z + be.z;
    o4.w = d3 * rstd * g.w + be.w;
    *(float4*)(out + base) = o4;
}

// ============================================================================
// Launch sequence (graph-capturable: kernel launches only)
// ============================================================================
extern "C" void kernel_launch(void* const* d_in, const int* in_sizes, int n_in,
                              void* d_out, int out_size)
{
    const float* tokens = (const float*)d_in[0];
    const float* Wq = (const float*)d_in[1];
    const float* bq = (const float*)d_in[2];
    const float* Wk = (const float*)d_in[3];
    const float* bk = (const float*)d_in[4];
    const float* Wv = (const float*)d_in[5];
    const float* bv = (const float*)d_in[6];
    const float* ds = (const float*)d_in[7];
    const float* W1 = (const float*)d_in[8];
    const float* b1 = (const float*)d_in[9];
    const float* W2 = (const float*)d_in[10];
    const float* b2 = (const float*)d_in[11];
    const float* g1 = (const float*)d_in[12];
    const float* be1 = (const float*)d_in[13];
    const float* g2 = (const float*)d_in[14];
    const float* be2 = (const float*)d_in[15];
    float* out = (float*)d_out;

    float *q, *k, *v, *attn, *x, *y, *h, *s;
    cudaGetSymbolAddress((void**)&q, g_q);
    cudaGetSymbolAddress((void**)&k, g_k);
    cudaGetSymbolAddress((void**)&v, g_v);
    cudaGetSymbolAddress((void**)&attn, g_attn);
    cudaGetSymbolAddress((void**)&x, g_x);
    cudaGetSymbolAddress((void**)&y, g_y);
    cudaGetSymbolAddress((void**)&h, g_h);
    cudaGetSymbolAddress((void**)&s, g_s);

    // QKV projections: [8192,512] = tokens[8192,512] @ W[512,512] + b
    dim3 gqkv(D_MODEL / 128, NTOK / 128, 1);
    gemm_nn<0, 0><<<gqkv, 256>>>(tokens, Wq, bq, q, NTOK, D_MODEL, D_MODEL, 0, 0, 0);
    gemm_nn<0, 0><<<gqkv, 256>>>(tokens, Wk, bk, k, NTOK, D_MODEL, D_MODEL, 0, 0, 0);
    gemm_nn<0, 0><<<gqkv, 256>>>(tokens, Wv, bv, v, NTOK, D_MODEL, D_MODEL, 0, 0, 0);

    // Raw scores: per-batch S[4096,4096] = Q @ K^T, above-diagonal tiles skipped
    gemm_nt_causal<<<dim3(TSEQ / 128, TSEQ / 128, NB), 256>>>(q, k, s, TSEQ, TSEQ, D_MODEL);

    // In-place masked softmax with distance bias + 1/sqrt(d)
    softmax_kernel<<<dim3(TSEQ, NB), 256>>>(s, ds);

    // attn_out = P @ V, K-loop clamped to causal extent per row-tile
    gemm_nn<0, 1><<<dim3(D_MODEL / 128, TSEQ / 128, NB), 256>>>(
        s, v, nullptr, attn, TSEQ, D_MODEL, TSEQ,
        (long)TSEQ * TSEQ, (long)TSEQ * D_MODEL, (long)TSEQ * D_MODEL);

    // x = LN(tokens + attn_out)
    ln_kernel<<<NTOK, 128>>>(tokens, attn, g1, be1, x);

    // h = relu(x @ W1 + b1)
    gemm_nn<1, 0><<<dim3(HDIM / 128, NTOK / 128, 1), 256>>>(
        x, W1, b1, h, NTOK, HDIM, D_MODEL, 0, 0, 0);

    // y = h @ W2 + b2
    gemm_nn<0, 0><<<dim3(D_MODEL / 128, NTOK / 128, 1), 256>>>(
        h, W2, b2, y, NTOK, D_MODEL, HDIM, 0, 0, 0);

    // z = LN(y + x)
    ln_kernel<<<NTOK, 128>>>(y, x, g2, be2, out);
}

// round 2
// speedup vs baseline: 2.8830x; 2.8830x over previous
#include <cuda_runtime.h>
#include <math.h>
#include <stdint.h>

// Problem constants
#define D_MODEL 512
#define HDIM    2048
#define TSEQ    4096
#define NB      2
#define NTOK    (NB * TSEQ)  // 8192

// -------- static scratch (allocation-free per harness rules) --------
__device__ float g_q[(size_t)NTOK * D_MODEL];
__device__ float g_k[(size_t)NTOK * D_MODEL];
__device__ float g_v[(size_t)NTOK * D_MODEL];
__device__ float g_attn[(size_t)NTOK * D_MODEL];
__device__ float g_x[(size_t)NTOK * D_MODEL];
__device__ float g_y[(size_t)NTOK * D_MODEL];
__device__ float g_h[(size_t)NTOK * HDIM];
__device__ float g_s[(size_t)NB * TSEQ * TSEQ];  // scores / probs (in-place softmax)

// ---------------------------------------------------------------------------
// tf32 helpers
// ---------------------------------------------------------------------------
__device__ __forceinline__ float to_tf32(float x) {
    uint32_t u;
    asm("cvt.rna.tf32.f32 %0, %1;" : "=r"(u) : "f"(x));
    return __uint_as_float(u);
}

__device__ __forceinline__ void mma_tf32(float c[4], const float a[4], const float b[2]) {
    asm volatile(
        "mma.sync.aligned.m16n8k8.row.col.f32.tf32.tf32.f32 "
        "{%0,%1,%2,%3}, {%4,%5,%6,%7}, {%8,%9}, {%0,%1,%2,%3};"
        : "+f"(c[0]), "+f"(c[1]), "+f"(c[2]), "+f"(c[3])
        : "r"(__float_as_uint(a[0])), "r"(__float_as_uint(a[1])),
          "r"(__float_as_uint(a[2])), "r"(__float_as_uint(a[3])),
          "r"(__float_as_uint(b[0])), "r"(__float_as_uint(b[1])));
}

// ============================================================================
// tf32 tensor-core GEMM: C = A(MxK) @ B [+bias] [relu].
//   TRANSB=0: B is KxN row-major.   TRANSB=1: B is NxK row-major (C=A@B^T),
//             and above-diagonal 128x128 tiles are skipped (causal scores).
//   KLIMIT=1: K clamped to (blockIdx.y+1)*128 (causal P@V).
// Block 128x128, BK=32, 256 threads (8 warps, each 64x32 via m16n8k8).
// Smem: A[128][36] ([m][k], bank=4m+k -> conflict-free frag loads)
//       B NN: [32][136] ([k][n], bank=8k+n), NT: [128][36] ([n][k]).
// ============================================================================
template <int RELU, int KLIMIT, int TRANSB>
__global__ __launch_bounds__(256, 2) void gemm_tf32(
    const float* __restrict__ Aall, const float* __restrict__ Ball,
    const float* __restrict__ bias, float* __restrict__ Call,
    int M, int N, int K, long sA, long sB, long sC)
{
    if (TRANSB && blockIdx.x > blockIdx.y) return;  // fully-masked score tile

    __shared__ __align__(16) float As[128 * 36];
    __shared__ __align__(16) float Bs[128 * 36];  // NN uses 32*136 <= 128*36

    const float* A = Aall + (size_t)blockIdx.z * sA;
    const float* B = Ball + (size_t)blockIdx.z * sB;
    float*       C = Call + (size_t)blockIdx.z * sC;

    const int tid  = threadIdx.x;
    const int m0   = blockIdx.y * 128;
    const int n0   = blockIdx.x * 128;
    const int Keff = KLIMIT ? min(K, ((int)blockIdx.y + 1) * 128) : K;

    const int lane = tid & 31;
    const int gid  = lane >> 2;   // 0..7
    const int tg   = lane & 3;    // 0..3
    const int warp = tid >> 5;
    const int mw   = (warp >> 2) * 64;  // warp row offset
    const int nw   = (warp & 3) * 32;   // warp col offset

    float acc[4][4][4];
#pragma unroll
    for (int i = 0; i < 4; i++)
#pragma unroll
        for (int j = 0; j < 4; j++)
#pragma unroll
            for (int r = 0; r < 4; r++) acc[i][j][r] = 0.f;

    for (int kt = 0; kt < Keff; kt += 32) {
        // ---- load A tile 128x32, tf32-convert, store [m][k] stride 36 ----
#pragma unroll
        for (int i = 0; i < 4; i++) {
            int idx = tid + i * 256;
            int row = idx >> 3;
            int c4  = (idx & 7) << 2;
            float4 v = *(const float4*)(A + (size_t)(m0 + row) * K + kt + c4);
            float4 w;
            w.x = to_tf32(v.x); w.y = to_tf32(v.y);
            w.z = to_tf32(v.z); w.w = to_tf32(v.w);
            *(float4*)&As[row * 36 + c4] = w;
        }
        // ---- load B tile ----
        if (TRANSB) {
            // B is NxK; tile rows are n (128), cols are k (32); store [n][k]
#pragma unroll
            for (int i = 0; i < 4; i++) {
                int idx = tid + i * 256;
                int row = idx >> 3;
                int c4  = (idx & 7) << 2;
                float4 v = *(const float4*)(B + (size_t)(n0 + row) * K + kt + c4);
                float4 w;
                w.x = to_tf32(v.x); w.y = to_tf32(v.y);
                w.z = to_tf32(v.z); w.w = to_tf32(v.w);
                *(float4*)&Bs[row * 36 + c4] = w;
            }
        } else {
            // B is KxN; tile rows are k (32), cols are n (128); store [k][n] stride 136
#pragma unroll
            for (int i = 0; i < 4; i++) {
                int idx = tid + i * 256;
                int kr  = idx >> 5;
                int nc  = (idx & 31) << 2;
                float4 v = *(const float4*)(B + (size_t)(kt + kr) * N + n0 + nc);
                float4 w;
                w.x = to_tf32(v.x); w.y = to_tf32(v.y);
                w.z = to_tf32(v.z); w.w = to_tf32(v.w);
                *(float4*)&Bs[kr * 136 + nc] = w;
            }
        }
        __syncthreads();

#pragma unroll
        for (int ks = 0; ks < 4; ks++) {
            const int kk = ks * 8;
            float a[4][4];
#pragma unroll
            for (int i = 0; i < 4; i++) {
                int mb = (mw + i * 16 + gid) * 36;
                a[i][0] = As[mb + kk + tg];
                a[i][1] = As[mb + 8 * 36 + kk + tg];
                a[i][2] = As[mb + kk + tg + 4];
                a[i][3] = As[mb + 8 * 36 + kk + tg + 4];
            }
            float b[4][2];
#pragma unroll
            for (int j = 0; j < 4; j++) {
                if (TRANSB) {
                    int nb = (nw + j * 8 + gid) * 36;
                    b[j][0] = Bs[nb + kk + tg];
                    b[j][1] = Bs[nb + kk + tg + 4];
                } else {
                    b[j][0] = Bs[(kk + tg) * 136 + nw + j * 8 + gid];
                    b[j][1] = Bs[(kk + tg + 4) * 136 + nw + j * 8 + gid];
                }
            }
#pragma unroll
            for (int i = 0; i < 4; i++)
#pragma unroll
                for (int j = 0; j < 4; j++) mma_tf32(acc[i][j], a[i], b[j]);
        }
        __syncthreads();
    }

    // ---- epilogue: c0/c1 -> (m, n..n+1), c2/c3 -> (m+8, n..n+1) ----
#pragma unroll
    for (int i = 0; i < 4; i++) {
        int m = m0 + mw + i * 16 + gid;
#pragma unroll
        for (int j = 0; j < 4; j++) {
            int n = n0 + nw + j * 8 + tg * 2;
            float2 lo = make_float2(acc[i][j][0], acc[i][j][1]);
            float2 hi = make_float2(acc[i][j][2], acc[i][j][3]);
            if (bias) {
                float b0 = bias[n], b1 = bias[n + 1];
                lo.x += b0; lo.y += b1; hi.x += b0; hi.y += b1;
            }
            if (RELU) {
                lo.x = fmaxf(lo.x, 0.f); lo.y = fmaxf(lo.y, 0.f);
                hi.x = fmaxf(hi.x, 0.f); hi.y = fmaxf(hi.y, 0.f);
            }
            *(float2*)(C + (size_t)m * N + n) = lo;
            *(float2*)(C + (size_t)(m + 8) * N + n) = hi;
        }
    }
}

// ---------------------------------------------------------------------------
// FMA-only exp (avoids MUFU bottleneck). Input expected <= 0; clamped.
// 2^t polynomial on t in [-0.5, 0.5], exact exponent via bit trick.
// ---------------------------------------------------------------------------
__device__ __forceinline__ float fast_exp(float x) {
    x = fmaxf(x, -87.0f);
    float z = x * 1.4426950408889634f;   // x * log2(e)
    float n = rintf(z);
    float t = z - n;
    // exp(t*ln2), |t|<=0.5, degree-6, rel err ~6e-8
    float p = 1.5403530e-4f;
    p = fmaf(p, t, 1.3333558e-3f);
    p = fmaf(p, t, 9.6181291e-3f);
    p = fmaf(p, t, 5.5504109e-2f);
    p = fmaf(p, t, 2.4022651e-1f);
    p = fmaf(p, t, 6.9314718e-1f);
    p = fmaf(p, t, 1.0f);
    int e = (int)n;
    return p * __int_as_float((e + 127) << 23);
}

// ============================================================================
// Row softmax (in-place), register-resident (16 vals/thread, no smem buffer):
// P[t,s] = softmax_{s<=t}((S - ds*(t-s)) / sqrt(d)); zeros written only up to
// the next 128 boundary (PV's KLIMIT never reads past it).
// ============================================================================
__global__ __launch_bounds__(256) void softmax_kernel(
    float* __restrict__ S, const float* __restrict__ ds_ptr)
{
    __shared__ float red[8];

    const int t = blockIdx.x;
    const int b = blockIdx.y;
    const int tid = threadIdx.x;
    const int lane = tid & 31;
    const int wid  = tid >> 5;
    float* row = S + ((size_t)b * TSEQ + t) * TSEQ;

    const float ds = *ds_ptr;
    const float scale = rsqrtf((float)D_MODEL);
    const int len = t + 1;
    const int limit = ((t >> 7) + 1) << 7;  // next 128 boundary

    float v[16];
    float mx = -1e30f;
#pragma unroll
    for (int it = 0; it < 16; it++) {
        int s = tid + it * 256;
        float val = -1e30f;
        if (s < len) val = (row[s] - ds * (float)(t - s)) * scale;
        v[it] = val;
        mx = fmaxf(mx, val);
    }
#pragma unroll
    for (int o = 16; o; o >>= 1) mx = fmaxf(mx, __shfl_xor_sync(0xffffffffu, mx, o));
    if (lane == 0) red[wid] = mx;
    __syncthreads();
    float mall = -1e30f;
#pragma unroll
    for (int w = 0; w < 8; w++) mall = fmaxf(mall, red[w]);
    __syncthreads();

    float sum = 0.f;
#pragma unroll
    for (int it = 0; it < 16; it++) {
        int s = tid + it * 256;
        float e = (s < len) ? fast_exp(v[it] - mall) : 0.f;
        v[it] = e;
        sum += e;
    }
#pragma unroll
    for (int o = 16; o; o >>= 1) sum += __shfl_xor_sync(0xffffffffu, sum, o);
    if (lane == 0) red[wid] = sum;
    __syncthreads();
    float sall = 0.f;
#pragma unroll
    for (int w = 0; w < 8; w++) sall += red[w];
    const float inv = 1.0f / sall;

#pragma unroll
    for (int it = 0; it < 16; it++) {
        int s = tid + it * 256;
        if (s < len)        row[s] = v[it] * inv;
        else if (s < limit) row[s] = 0.f;
    }
}

// ============================================================================
// LayerNorm over last dim (512): out = LN(A + R) * gamma + beta.
// ============================================================================
__global__ __launch_bounds__(128) void ln_kernel(
    const float* __restrict__ A, const float* __restrict__ R,
    const float* __restrict__ gamma, const float* __restrict__ beta,
    float* __restrict__ out)
{
    __shared__ float sh[4];
    const int row = blockIdx.x;
    const int tid = threadIdx.x;
    const size_t base = (size_t)row * D_MODEL + tid * 4;

    float4 a = *(const float4*)(A + base);
    float4 r = *(const float4*)(R + base);
    float x0 = a.x + r.x, x1 = a.y + r.y, x2 = a.z + r.z, x3 = a.w + r.w;

    float s = x0 + x1 + x2 + x3;
    for (int o = 16; o; o >>= 1) s += __shfl_xor_sync(0xffffffffu, s, o);
    if ((tid & 31) == 0) sh[tid >> 5] = s;
    __syncthreads();
    const float mean = (sh[0] + sh[1] + sh[2] + sh[3]) * (1.0f / D_MODEL);
    __syncthreads();

    float d0 = x0 - mean, d1 = x1 - mean, d2 = x2 - mean, d3 = x3 - mean;
    float sq = d0 * d0 + d1 * d1 + d2 * d2 + d3 * d3;
    for (int o = 16; o; o >>= 1) sq += __shfl_xor_sync(0xffffffffu, sq, o);
    if ((tid & 31) == 0) sh[tid >> 5] = sq;
    __syncthreads();
    const float var = (sh[0] + sh[1] + sh[2] + sh[3]) * (1.0f / D_MODEL);
    const float rstd = rsqrtf(var + 1e-5f);

    float4 g  = *(const float4*)(gamma + tid * 4);
    float4 be = *(const float4*)(beta + tid * 4);
    float4 o4;
    o4.x = d0 * rstd * g.x + be.x;
    o4.y = d1 * rstd * g.y + be.y;
    o4.z = d2 * rstd * g.z + be.z;
    o4.w = d3 * rstd * g.w + be.w;
    *(float4*)(out + base) = o4;
}

// ============================================================================
// Launch sequence (graph-capturable: kernel launches only)
// ============================================================================
extern "C" void kernel_launch(void* const* d_in, const int* in_sizes, int n_in,
                              void* d_out, int out_size)
{
    const float* tokens = (const float*)d_in[0];
    const float* Wq = (const float*)d_in[1];
    const float* bq = (const float*)d_in[2];
    const float* Wk = (const float*)d_in[3];
    const float* bk = (const float*)d_in[4];
    const float* Wv = (const float*)d_in[5];
    const float* bv = (const float*)d_in[6];
    const float* ds = (const float*)d_in[7];
    const float* W1 = (const float*)d_in[8];
    const float* b1 = (const float*)d_in[9];
    const float* W2 = (const float*)d_in[10];
    const float* b2 = (const float*)d_in[11];
    const float* g1 = (const float*)d_in[12];
    const float* be1 = (const float*)d_in[13];
    const float* g2 = (const float*)d_in[14];
    const float* be2 = (const float*)d_in[15];
    float* out = (float*)d_out;

    float *q, *k, *v, *attn, *x, *y, *h, *s;
    cudaGetSymbolAddress((void**)&q, g_q);
    cudaGetSymbolAddress((void**)&k, g_k);
    cudaGetSymbolAddress((void**)&v, g_v);
    cudaGetSymbolAddress((void**)&attn, g_attn);
    cudaGetSymbolAddress((void**)&x, g_x);
    cudaGetSymbolAddress((void**)&y, g_y);
    cudaGetSymbolAddress((void**)&h, g_h);
    cudaGetSymbolAddress((void**)&s, g_s);

    // QKV projections: [8192,512] = tokens @ W + b
    dim3 gqkv(D_MODEL / 128, NTOK / 128, 1);
    gemm_tf32<0, 0, 0><<<gqkv, 256>>>(tokens, Wq, bq, q, NTOK, D_MODEL, D_MODEL, 0, 0, 0);
    gemm_tf32<0, 0, 0><<<gqkv, 256>>>(tokens, Wk, bk, k, NTOK, D_MODEL, D_MODEL, 0, 0, 0);
    gemm_tf32<0, 0, 0><<<gqkv, 256>>>(tokens, Wv, bv, v, NTOK, D_MODEL, D_MODEL, 0, 0, 0);

    // Raw scores: per-batch S = Q @ K^T (above-diagonal tiles skipped)
    gemm_tf32<0, 0, 1><<<dim3(TSEQ / 128, TSEQ / 128, NB), 256>>>(
        q, k, nullptr, s, TSEQ, TSEQ, D_MODEL,
        (long)TSEQ * D_MODEL, (long)TSEQ * D_MODEL, (long)TSEQ * TSEQ);

    // In-place masked softmax with distance bias + 1/sqrt(d)
    softmax_kernel<<<dim3(TSEQ, NB), 256>>>(s, ds);

    // attn_out = P @ V, K clamped to causal extent per row-tile
    gemm_tf32<0, 1, 0><<<dim3(D_MODEL / 128, TSEQ / 128, NB), 256>>>(
        s, v, nullptr, attn, TSEQ, D_MODEL, TSEQ,
        (long)TSEQ * TSEQ, (long)TSEQ * D_MODEL, (long)TSEQ * D_MODEL);

    // x = LN(tokens + attn_out)
    ln_kernel<<<NTOK, 128>>>(tokens, attn, g1, be1, x);

    // h = relu(x @ W1 + b1)
    gemm_tf32<1, 0, 0><<<dim3(HDIM / 128, NTOK / 128, 1), 256>>>(
        x, W1, b1, h, NTOK, HDIM, D_MODEL, 0, 0, 0);

    // y = h @ W2 + b2
    gemm_tf32<0, 0, 0><<<dim3(D_MODEL / 128, NTOK / 128, 1), 256>>>(
        h, W2, b2, y, NTOK, D_MODEL, HDIM, 0, 0, 0);

    // z = LN(y + x)
    ln_kernel<<<NTOK, 128>>>(y, x, g2, be2, out);
}

// round 3
// speedup vs baseline: 3.3265x; 1.1538x over previous
#include <cuda_runtime.h>
#include <math.h>
#include <stdint.h>

// Problem constants
#define D_MODEL 512
#define HDIM    2048
#define TSEQ    4096
#define NB      2
#define NTOK    (NB * TSEQ)  // 8192

#define STAGE_FLOATS 9216          // A(128*36=4608) + B(<=4608) per stage
#define SMEM_BYTES   (2 * STAGE_FLOATS * 4)  // 73728

// -------- static scratch (allocation-free per harness rules) --------
__device__ float g_q[(size_t)NTOK * D_MODEL];
__device__ float g_k[(size_t)NTOK * D_MODEL];
__device__ float g_v[(size_t)NTOK * D_MODEL];
__device__ float g_attn[(size_t)NTOK * D_MODEL];
__device__ float g_x[(size_t)NTOK * D_MODEL];
__device__ float g_y[(size_t)NTOK * D_MODEL];
__device__ float g_h[(size_t)NTOK * HDIM];
__device__ float g_s[(size_t)NB * TSEQ * TSEQ];
// tf32-pre-rounded copies of raw inputs
__device__ float g_tokr[(size_t)NTOK * D_MODEL];
__device__ float g_wq[(size_t)D_MODEL * D_MODEL];
__device__ float g_wk[(size_t)D_MODEL * D_MODEL];
__device__ float g_wv[(size_t)D_MODEL * D_MODEL];
__device__ float g_w1[(size_t)D_MODEL * HDIM];
__device__ float g_w2[(size_t)HDIM * D_MODEL];

// ---------------------------------------------------------------------------
// helpers
// ---------------------------------------------------------------------------
__device__ __forceinline__ float to_tf32(float x) {
    uint32_t u;
    asm("cvt.rna.tf32.f32 %0, %1;" : "=r"(u) : "f"(x));
    return __uint_as_float(u);
}

__device__ __forceinline__ void mma_tf32(float c[4], const float a[4], const float b[2]) {
    asm volatile(
        "mma.sync.aligned.m16n8k8.row.col.f32.tf32.tf32.f32 "
        "{%0,%1,%2,%3}, {%4,%5,%6,%7}, {%8,%9}, {%0,%1,%2,%3};"
        : "+f"(c[0]), "+f"(c[1]), "+f"(c[2]), "+f"(c[3])
        : "r"(__float_as_uint(a[0])), "r"(__float_as_uint(a[1])),
          "r"(__float_as_uint(a[2])), "r"(__float_as_uint(a[3])),
          "r"(__float_as_uint(b[0])), "r"(__float_as_uint(b[1])));
}

__device__ __forceinline__ uint32_t smem_u32(const void* p) {
    return (uint32_t)__cvta_generic_to_shared(p);
}
__device__ __forceinline__ void cp16(uint32_t d, const void* s) {
    asm volatile("cp.async.cg.shared.global [%0], [%1], 16;" :: "r"(d), "l"(s));
}
__device__ __forceinline__ void cp_commit() {
    asm volatile("cp.async.commit_group;");
}
template <int N>
__device__ __forceinline__ void cp_wait() {
    asm volatile("cp.async.wait_group %0;" :: "n"(N));
}

// ============================================================================
// tf32 tensor-core GEMM body, cp.async 2-stage pipeline.
// All inputs must already be tf32-representable (HMMA truncation is then
// lossless). Block 128x128, BK=32, 256 threads, 8 warps of 64x32 (m16n8k8).
//   TRANSB=0: B is KxN; smem [k][n] stride 136.  TRANSB=1: B is NxK; [n][k] s36.
//   KLIMIT=1: K clamped to (blockIdx.y+1)*128 (causal P@V).
//   ROUND_OUT=1: epilogue rounds output to tf32 (rna).
// ============================================================================
template <int RELU, int KLIMIT, int TRANSB, int ROUND_OUT>
__device__ __forceinline__ void gemm_body(
    const float* __restrict__ A, const float* __restrict__ B,
    const float* __restrict__ bias, float* __restrict__ C,
    int M, int N, int K)
{
    extern __shared__ float smem[];
    const int tid = threadIdx.x;
    const int m0 = blockIdx.y * 128;
    const int n0 = blockIdx.x * 128;
    const int Keff = KLIMIT ? min(K, ((int)blockIdx.y + 1) * 128) : K;
    const int NUMK = Keff >> 5;  // always >= 4 here

    const int lane = tid & 31;
    const int gid  = lane >> 2;
    const int tg   = lane & 3;
    const int warp = tid >> 5;
    const int mw   = (warp >> 2) * 64;
    const int nw   = (warp & 3) * 32;

    auto load_stage = [&](int s) {
        float* As = smem + (s & 1) * STAGE_FLOATS;
        float* Bs = As + 4608;
        const int kt = s << 5;
#pragma unroll
        for (int i = 0; i < 4; i++) {
            int idx = tid + i * 256;
            int row = idx >> 3;
            int c4  = (idx & 7) << 2;
            cp16(smem_u32(As + row * 36 + c4), A + (size_t)(m0 + row) * K + kt + c4);
            if (TRANSB) {
                cp16(smem_u32(Bs + row * 36 + c4), B + (size_t)(n0 + row) * K + kt + c4);
            } else {
                int kr = idx >> 5;
                int nc = (idx & 31) << 2;
                cp16(smem_u32(Bs + kr * 136 + nc), B + (size_t)(kt + kr) * N + n0 + nc);
            }
        }
    };

    float acc[4][4][4] = {};

    load_stage(0); cp_commit();
    load_stage(1); cp_commit();

    for (int k = 0; k < NUMK; k++) {
        cp_wait<1>();
        __syncthreads();
        const float* As = smem + (k & 1) * STAGE_FLOATS;
        const float* Bs = As + 4608;

#pragma unroll
        for (int ks = 0; ks < 4; ks++) {
            const int kk = ks * 8;
            float a[4][4];
#pragma unroll
            for (int i = 0; i < 4; i++) {
                int mb = (mw + i * 16 + gid) * 36;
                a[i][0] = As[mb + kk + tg];
                a[i][1] = As[mb + 8 * 36 + kk + tg];
                a[i][2] = As[mb + kk + tg + 4];
                a[i][3] = As[mb + 8 * 36 + kk + tg + 4];
            }
            float b[4][2];
#pragma unroll
            for (int j = 0; j < 4; j++) {
                if (TRANSB) {
                    int nb = (nw + j * 8 + gid) * 36;
                    b[j][0] = Bs[nb + kk + tg];
                    b[j][1] = Bs[nb + kk + tg + 4];
                } else {
                    b[j][0] = Bs[(kk + tg) * 136 + nw + j * 8 + gid];
                    b[j][1] = Bs[(kk + tg + 4) * 136 + nw + j * 8 + gid];
                }
            }
#pragma unroll
            for (int i = 0; i < 4; i++)
#pragma unroll
                for (int j = 0; j < 4; j++) mma_tf32(acc[i][j], a[i], b[j]);
        }
        __syncthreads();
        if (k + 2 < NUMK) load_stage(k + 2);
        cp_commit();
    }

#pragma unroll
    for (int i = 0; i < 4; i++) {
        int m = m0 + mw + i * 16 + gid;
#pragma unroll
        for (int j = 0; j < 4; j++) {
            int n = n0 + nw + j * 8 + tg * 2;
            float2 lo = make_float2(acc[i][j][0], acc[i][j][1]);
            float2 hi = make_float2(acc[i][j][2], acc[i][j][3]);
            if (bias) {
                float b0 = bias[n], b1 = bias[n + 1];
                lo.x += b0; lo.y += b1; hi.x += b0; hi.y += b1;
            }
            if (RELU) {
                lo.x = fmaxf(lo.x, 0.f); lo.y = fmaxf(lo.y, 0.f);
                hi.x = fmaxf(hi.x, 0.f); hi.y = fmaxf(hi.y, 0.f);
            }
            if (ROUND_OUT) {
                lo.x = to_tf32(lo.x); lo.y = to_tf32(lo.y);
                hi.x = to_tf32(hi.x); hi.y = to_tf32(hi.y);
            }
            *(float2*)(C + (size_t)m * N + n) = lo;
            *(float2*)(C + (size_t)(m + 8) * N + n) = hi;
        }
    }
}

template <int RELU, int KLIMIT, int TRANSB, int ROUND_OUT>
__global__ __launch_bounds__(256, 2) void gemm_tc(
    const float* __restrict__ Aall, const float* __restrict__ Ball,
    const float* __restrict__ bias, float* __restrict__ Call,
    int M, int N, int K, long sA, long sB, long sC)
{
    if (TRANSB && blockIdx.x > blockIdx.y) return;  // fully-masked score tile
    gemm_body<RELU, KLIMIT, TRANSB, ROUND_OUT>(
        Aall + (size_t)blockIdx.z * sA, Ball + (size_t)blockIdx.z * sB,
        bias, Call + (size_t)blockIdx.z * sC, M, N, K);
}

// Fused QKV: one launch, blockIdx.z selects projection.
__global__ __launch_bounds__(256, 2) void qkv_kernel(
    const float* __restrict__ tok,
    const float* __restrict__ Wq, const float* __restrict__ Wk, const float* __restrict__ Wv,
    const float* __restrict__ bq, const float* __restrict__ bk, const float* __restrict__ bv,
    float* __restrict__ q, float* __restrict__ k, float* __restrict__ v)
{
    const float* W = blockIdx.z == 0 ? Wq : (blockIdx.z == 1 ? Wk : Wv);
    const float* b = blockIdx.z == 0 ? bq : (blockIdx.z == 1 ? bk : bv);
    float*       C = blockIdx.z == 0 ? q  : (blockIdx.z == 1 ? k  : v);
    gemm_body<0, 0, 0, 1>(tok, W, b, C, NTOK, D_MODEL, D_MODEL);
}

// Pre-round raw inputs to tf32 (rna), vectorized.
__global__ __launch_bounds__(256) void round_kernel(
    const float* __restrict__ in, float* __restrict__ out, int n4)
{
    int i = blockIdx.x * 256 + threadIdx.x;
    if (i < n4) {
        float4 v = ((const float4*)in)[i];
        v.x = to_tf32(v.x); v.y = to_tf32(v.y);
        v.z = to_tf32(v.z); v.w = to_tf32(v.w);
        ((float4*)out)[i] = v;
    }
}

// ---------------------------------------------------------------------------
// FMA-only exp (input <= 0 after max-subtract; clamped).
// ---------------------------------------------------------------------------
__device__ __forceinline__ float fast_exp(float x) {
    x = fmaxf(x, -87.0f);
    float z = x * 1.4426950408889634f;
    float n = rintf(z);
    float t = z - n;
    float p = 1.5403530e-4f;
    p = fmaf(p, t, 1.3333558e-3f);
    p = fmaf(p, t, 9.6181291e-3f);
    p = fmaf(p, t, 5.5504109e-2f);
    p = fmaf(p, t, 2.4022651e-1f);
    p = fmaf(p, t, 6.9314718e-1f);
    p = fmaf(p, t, 1.0f);
    int e = (int)n;
    return p * __int_as_float((e + 127) << 23);
}

// ============================================================================
// Row softmax (in-place, register-resident). Output rounded to tf32 so the
// PV GEMM's cp.async truncation is lossless. Zeros written up to next 128.
// ============================================================================
__global__ __launch_bounds__(256) void softmax_kernel(
    float* __restrict__ S, const float* __restrict__ ds_ptr)
{
    __shared__ float red[8];

    const int t = blockIdx.x;
    const int b = blockIdx.y;
    const int tid = threadIdx.x;
    const int lane = tid & 31;
    const int wid  = tid >> 5;
    float* row = S + ((size_t)b * TSEQ + t) * TSEQ;

    const float ds = *ds_ptr;
    const float scale = rsqrtf((float)D_MODEL);
    const int len = t + 1;
    const int limit = ((t >> 7) + 1) << 7;

    float v[16];
    float mx = -1e30f;
#pragma unroll
    for (int it = 0; it < 16; it++) {
        int s = tid + it * 256;
        float val = -1e30f;
        if (s < len) val = (row[s] - ds * (float)(t - s)) * scale;
        v[it] = val;
        mx = fmaxf(mx, val);
    }
#pragma unroll
    for (int o = 16; o; o >>= 1) mx = fmaxf(mx, __shfl_xor_sync(0xffffffffu, mx, o));
    if (lane == 0) red[wid] = mx;
    __syncthreads();
    float mall = -1e30f;
#pragma unroll
    for (int w = 0; w < 8; w++) mall = fmaxf(mall, red[w]);
    __syncthreads();

    float sum = 0.f;
#pragma unroll
    for (int it = 0; it < 16; it++) {
        int s = tid + it * 256;
        float e = (s < len) ? fast_exp(v[it] - mall) : 0.f;
        v[it] = e;
        sum += e;
    }
#pragma unroll
    for (int o = 16; o; o >>= 1) sum += __shfl_xor_sync(0xffffffffu, sum, o);
    if (lane == 0) red[wid] = sum;
    __syncthreads();
    float sall = 0.f;
#pragma unroll
    for (int w = 0; w < 8; w++) sall += red[w];
    const float inv = 1.0f / sall;

#pragma unroll
    for (int it = 0; it < 16; it++) {
        int s = tid + it * 256;
        if (s < len)        row[s] = to_tf32(v[it] * inv);
        else if (s < limit) row[s] = 0.f;
    }
}

// ============================================================================
// LayerNorm over last dim (512): out = LN(A + R) * gamma + beta.
// ROUND=1 rounds the output to tf32 (feeds a GEMM).
// ============================================================================
template <int ROUND>
__global__ __launch_bounds__(128) void ln_kernel(
    const float* __restrict__ A, const float* __restrict__ R,
    const float* __restrict__ gamma, const float* __restrict__ beta,
    float* __restrict__ out)
{
    __shared__ float sh[4];
    const int row = blockIdx.x;
    const int tid = threadIdx.x;
    const size_t base = (size_t)row * D_MODEL + tid * 4;

    float4 a = *(const float4*)(A + base);
    float4 r = *(const float4*)(R + base);
    float x0 = a.x + r.x, x1 = a.y + r.y, x2 = a.z + r.z, x3 = a.w + r.w;

    float s = x0 + x1 + x2 + x3;
    for (int o = 16; o; o >>= 1) s += __shfl_xor_sync(0xffffffffu, s, o);
    if ((tid & 31) == 0) sh[tid >> 5] = s;
    __syncthreads();
    const float mean = (sh[0] + sh[1] + sh[2] + sh[3]) * (1.0f / D_MODEL);
    __syncthreads();

    float d0 = x0 - mean, d1 = x1 - mean, d2 = x2 - mean, d3 = x3 - mean;
    float sq = d0 * d0 + d1 * d1 + d2 * d2 + d3 * d3;
    for (int o = 16; o; o >>= 1) sq += __shfl_xor_sync(0xffffffffu, sq, o);
    if ((tid & 31) == 0) sh[tid >> 5] = sq;
    __syncthreads();
    const float var = (sh[0] + sh[1] + sh[2] + sh[3]) * (1.0f / D_MODEL);
    const float rstd = rsqrtf(var + 1e-5f);

    float4 g  = *(const float4*)(gamma + tid * 4);
    float4 be = *(const float4*)(beta + tid * 4);
    float4 o4;
    o4.x = d0 * rstd * g.x + be.x;
    o4.y = d1 * rstd * g.y + be.y;
    o4.z = d2 * rstd * g.z + be.z;
    o4.w = d3 * rstd * g.w + be.w;
    if (ROUND) {
        o4.x = to_tf32(o4.x); o4.y = to_tf32(o4.y);
        o4.z = to_tf32(o4.z); o4.w = to_tf32(o4.w);
    }
    *(float4*)(out + base) = o4;
}

// ============================================================================
// Launch sequence (graph-capturable)
// ============================================================================
extern "C" void kernel_launch(void* const* d_in, const int* in_sizes, int n_in,
                              void* d_out, int out_size)
{
    const float* tokens = (const float*)d_in[0];
    const float* Wq = (const float*)d_in[1];
    const float* bq = (const float*)d_in[2];
    const float* Wk = (const float*)d_in[3];
    const float* bk = (const float*)d_in[4];
    const float* Wv = (const float*)d_in[5];
    const float* bv = (const float*)d_in[6];
    const float* ds = (const float*)d_in[7];
    const float* W1 = (const float*)d_in[8];
    const float* b1 = (const float*)d_in[9];
    const float* W2 = (const float*)d_in[10];
    const float* b2 = (const float*)d_in[11];
    const float* g1 = (const float*)d_in[12];
    const float* be1 = (const float*)d_in[13];
    const float* g2 = (const float*)d_in[14];
    const float* be2 = (const float*)d_in[15];
    float* out = (float*)d_out;

    float *q, *k, *v, *attn, *x, *y, *h, *s;
    float *tokr, *wq, *wk, *wv, *w1, *w2;
    cudaGetSymbolAddress((void**)&q, g_q);
    cudaGetSymbolAddress((void**)&k, g_k);
    cudaGetSymbolAddress((void**)&v, g_v);
    cudaGetSymbolAddress((void**)&attn, g_attn);
    cudaGetSymbolAddress((void**)&x, g_x);
    cudaGetSymbolAddress((void**)&y, g_y);
    cudaGetSymbolAddress((void**)&h, g_h);
    cudaGetSymbolAddress((void**)&s, g_s);
    cudaGetSymbolAddress((void**)&tokr, g_tokr);
    cudaGetSymbolAddress((void**)&wq, g_wq);
    cudaGetSymbolAddress((void**)&wk, g_wk);
    cudaGetSymbolAddress((void**)&wv, g_wv);
    cudaGetSymbolAddress((void**)&w1, g_w1);
    cudaGetSymbolAddress((void**)&w2, g_w2);

    // Raise dynamic smem limit for GEMM kernels (idempotent, capture-safe).
    cudaFuncSetAttribute(qkv_kernel, cudaFuncAttributeMaxDynamicSharedMemorySize, SMEM_BYTES);
    cudaFuncSetAttribute(gemm_tc<0, 0, 1, 0>, cudaFuncAttributeMaxDynamicSharedMemorySize, SMEM_BYTES);
    cudaFuncSetAttribute(gemm_tc<0, 1, 0, 0>, cudaFuncAttributeMaxDynamicSharedMemorySize, SMEM_BYTES);
    cudaFuncSetAttribute(gemm_tc<1, 0, 0, 1>, cudaFuncAttributeMaxDynamicSharedMemorySize, SMEM_BYTES);
    cudaFuncSetAttribute(gemm_tc<0, 0, 0, 0>, cudaFuncAttributeMaxDynamicSharedMemorySize, SMEM_BYTES);

    // --- pre-round raw GEMM inputs to tf32 (rna) ---
    round_kernel<<<(NTOK * D_MODEL / 4 + 255) / 256, 256>>>(tokens, tokr, NTOK * D_MODEL / 4);
    round_kernel<<<(D_MODEL * D_MODEL / 4 + 255) / 256, 256>>>(Wq, wq, D_MODEL * D_MODEL / 4);
    round_kernel<<<(D_MODEL * D_MODEL / 4 + 255) / 256, 256>>>(Wk, wk, D_MODEL * D_MODEL / 4);
    round_kernel<<<(D_MODEL * D_MODEL / 4 + 255) / 256, 256>>>(Wv, wv, D_MODEL * D_MODEL / 4);
    round_kernel<<<(D_MODEL * HDIM / 4 + 255) / 256, 256>>>(W1, w1, D_MODEL * HDIM / 4);
    round_kernel<<<(HDIM * D_MODEL / 4 + 255) / 256, 256>>>(W2, w2, HDIM * D_MODEL / 4);

    // --- QKV (fused; outputs tf32-rounded) ---
    qkv_kernel<<<dim3(D_MODEL / 128, NTOK / 128, 3), 256, SMEM_BYTES>>>(
        tokr, wq, wk, wv, bq, bk, bv, q, k, v);

    // --- raw scores S = Q @ K^T (above-diagonal tiles skipped) ---
    gemm_tc<0, 0, 1, 0><<<dim3(TSEQ / 128, TSEQ / 128, NB), 256, SMEM_BYTES>>>(
        q, k, nullptr, s, TSEQ, TSEQ, D_MODEL,
        (long)TSEQ * D_MODEL, (long)TSEQ * D_MODEL, (long)TSEQ * TSEQ);

    // --- masked softmax (distance bias + 1/sqrt(d)); outputs tf32-rounded ---
    softmax_kernel<<<dim3(TSEQ, NB), 256>>>(s, ds);

    // --- attn = P @ V, K clamped to causal extent ---
    gemm_tc<0, 1, 0, 0><<<dim3(D_MODEL / 128, TSEQ / 128, NB), 256, SMEM_BYTES>>>(
        s, v, nullptr, attn, TSEQ, D_MODEL, TSEQ,
        (long)TSEQ * TSEQ, (long)TSEQ * D_MODEL, (long)TSEQ * D_MODEL);

    // --- x = LN(tokens + attn) (tf32-rounded; feeds FFN1 + residual) ---
    ln_kernel<1><<<NTOK, 128>>>(tokens, attn, g1, be1, x);

    // --- h = relu(x @ W1 + b1) (tf32-rounded) ---
    gemm_tc<1, 0, 0, 1><<<dim3(HDIM / 128, NTOK / 128, 1), 256, SMEM_BYTES>>>(
        x, w1, b1, h, NTOK, HDIM, D_MODEL, 0, 0, 0);

    // --- y = h @ W2 + b2 (full precision out) ---
    gemm_tc<0, 0, 0, 0><<<dim3(D_MODEL / 128, NTOK / 128, 1), 256, SMEM_BYTES>>>(
        h, w2, b2, y, NTOK, D_MODEL, HDIM, 0, 0, 0);

    // --- z = LN(y + x) ---
    ln_kernel<0><<<NTOK, 128>>>(y, x, g2, be2, out);
}